// round 7
// baseline (speedup 1.0000x reference)
#include <cuda_runtime.h>
#include <math.h>

#define Bsz  128
#define Tlen 1024
#define Hd   256
#define NOUT 2

typedef unsigned long long u64;

// Scratch buffers (device globals — allocation is forbidden)
__device__ float g_bufA[Bsz * Tlen * Hd];  // pre-activations
__device__ float g_bufB[Bsz * Tlen * Hd];  // layer-1 hidden states

// ---------- packed fp32x2 helpers (full-rate fp32 path on sm_103a) ----------
__device__ __forceinline__ void fma2(u64& acc, u64 a, u64 b) {
    asm("fma.rn.f32x2 %0, %1, %2, %0;" : "+l"(acc) : "l"(a), "l"(b));
}
__device__ __forceinline__ u64 add2(u64 a, u64 b) {
    u64 r; asm("add.rn.f32x2 %0, %1, %2;" : "=l"(r) : "l"(a), "l"(b)); return r;
}
__device__ __forceinline__ float2 unpk(u64 v) {
    float2 r; asm("mov.b64 {%0, %1}, %2;" : "=f"(r.x), "=f"(r.y) : "l"(v)); return r;
}

// =============================================================================
// GEMM (R6 version — known good, ~449us): out = A @ W^T + bias
// M=131072, N=K=256. Tile 128x128, 256 threads, K staged in 4 chunks of 64.
// A staged DUPLICATED so the m-operand loads as one LDS.64.
// =============================================================================
#define WS_STRIDE 130
#define AS_STRIDE 258
#define GEMM_SMEM ((Hd * WS_STRIDE + 64 * AS_STRIDE) * 4)

__global__ void __launch_bounds__(256, 1) gemm_kernel(
    const float* __restrict__ A, const float* __restrict__ W,
    const float* __restrict__ bias, float* __restrict__ out)
{
    extern __shared__ float sm[];
    float* Ws = sm;                    // [K=256][130]
    float* As = sm + Hd * WS_STRIDE;   // [64][258]

    const int t   = threadIdx.x;
    const int nt  = blockIdx.x & 1;
    const int mt  = blockIdx.x >> 1;
    const int m0  = mt * 128, n0 = nt * 128;
    const int kq  = t & 15;
    const int rn  = t >> 4;
    const int ml  = t & 15;
    const int tn2 = (t >> 4) << 1;

    const float4* W4 = (const float4*)(W + (size_t)n0 * Hd);
    #pragma unroll
    for (int p = 0; p < 8; ++p) {
        int row = rn + (p << 4);
        #pragma unroll
        for (int q = 0; q < 4; ++q) {
            float4 v = W4[row * 64 + (q << 4) + kq];
            int k = (((q << 4) + kq) << 2);
            Ws[(k + 0) * WS_STRIDE + row] = v.x;
            Ws[(k + 1) * WS_STRIDE + row] = v.y;
            Ws[(k + 2) * WS_STRIDE + row] = v.z;
            Ws[(k + 3) * WS_STRIDE + row] = v.w;
        }
    }

    u64 acc[8][4];
    #pragma unroll
    for (int i = 0; i < 8; ++i)
        #pragma unroll
        for (int j = 0; j < 4; ++j) acc[i][j] = 0ull;

    const float4* A4 = (const float4*)(A + (size_t)m0 * Hd);

    float4 v[8];
    #pragma unroll
    for (int p = 0; p < 8; ++p)
        v[p] = A4[(rn + (p << 4)) * 64 + kq];

    for (int s = 0; s < 4; ++s) {
        __syncthreads();
        #pragma unroll
        for (int p = 0; p < 8; ++p) {
            int row2 = (rn + (p << 4)) << 1;
            int k0 = kq << 2;
            *(float2*)&As[(k0 + 0) * AS_STRIDE + row2] = make_float2(v[p].x, v[p].x);
            *(float2*)&As[(k0 + 1) * AS_STRIDE + row2] = make_float2(v[p].y, v[p].y);
            *(float2*)&As[(k0 + 2) * AS_STRIDE + row2] = make_float2(v[p].z, v[p].z);
            *(float2*)&As[(k0 + 3) * AS_STRIDE + row2] = make_float2(v[p].w, v[p].w);
        }
        if (s < 3) {
            #pragma unroll
            for (int p = 0; p < 8; ++p)
                v[p] = A4[(rn + (p << 4)) * 64 + ((s + 1) << 4) + kq];
        }
        __syncthreads();

        const int kbase = s << 6;
        #pragma unroll 4
        for (int kk = 0; kk < 64; ++kk) {
            u64 ad[8];
            #pragma unroll
            for (int i = 0; i < 8; ++i)
                ad[i] = *(const u64*)&As[kk * AS_STRIDE + ((ml + (i << 4)) << 1)];
            u64 bp[4];
            #pragma unroll
            for (int j = 0; j < 4; ++j)
                bp[j] = *(const u64*)&Ws[(kbase + kk) * WS_STRIDE + tn2 + (j << 5)];
            #pragma unroll
            for (int i = 0; i < 8; ++i)
                #pragma unroll
                for (int j = 0; j < 4; ++j)
                    fma2(acc[i][j], ad[i], bp[j]);
        }
    }

    #pragma unroll
    for (int j = 0; j < 4; ++j) {
        int n = n0 + tn2 + (j << 5);
        float bv0 = bias[n], bv1 = bias[n + 1];
        #pragma unroll
        for (int i = 0; i < 8; ++i) {
            int m = m0 + ml + (i << 4);
            float2 vv = unpk(acc[i][j]);
            float2 r; r.x = vv.x + bv0; r.y = vv.y + bv1;
            *(float2*)&out[(size_t)m * Hd + n] = r;
        }
    }
}

// =============================================================================
// Recurrence v5: 1 CTA = 1 batch row, 1024 threads (32 warps).
// Thread t -> output j = t & 255, K-quarter kq = t >> 8 (warp-uniform).
// ALL 64 weights/thread in registers (16 float4 = 32 regs) -> ZERO smem
// weight traffic. h loads are single-address warp broadcasts (1 wf each).
// 4-way reduction via smem part[] with 2 barriers/step.
// =============================================================================
__device__ __forceinline__ float fast_tanh(float x) {
    float e = __expf(2.0f * x);
    return 1.0f - 2.0f * __fdividef(1.0f, e + 1.0f);
}

template<bool WRITE_H, bool FINAL>
__global__ void __launch_bounds__(1024, 1) recur_kernel(
    const float* __restrict__ pre, const float* __restrict__ Whh,
    float* __restrict__ hout,
    const float* __restrict__ fcw, const float* __restrict__ fcb,
    float* __restrict__ out)
{
    __shared__ float hbuf[2 * 256];   // ping-pong h
    __shared__ float part[3 * 256];   // partials from kq = 1..3

    const int t  = threadIdx.x;
    const int b  = blockIdx.x;
    const int j  = t & 255;
    const int kq = t >> 8;            // 0..3, uniform within each warp

    // This thread's 64 weights -> 16 ulonglong2 in registers
    const ulonglong2* wg =
        (const ulonglong2*)(Whh + (size_t)j * Hd + (kq << 6));
    ulonglong2 wr[16];
    #pragma unroll
    for (int c = 0; c < 16; ++c) wr[c] = wg[c];

    if (t < 512) hbuf[t] = 0.f;       // h0 = 0 in both parities

    const float* preb = pre + (size_t)b * Tlen * Hd;
    float p = (kq == 0) ? preb[j] : 0.f;
    __syncthreads();

    for (int step = 0; step < Tlen; ++step) {
        float pn = 0.f;
        if (kq == 0) {
            int sn = (step + 1 < Tlen) ? step + 1 : step;
            pn = preb[sn * Hd + j];   // prefetch next pre
        }

        const ulonglong2* hb =
            (const ulonglong2*)(hbuf + (step & 1) * 256 + (kq << 6));

        u64 a0 = 0ull, a1 = 0ull, a2 = 0ull, a3 = 0ull;
        #pragma unroll
        for (int c = 0; c < 16; c += 2) {
            ulonglong2 hv = hb[c];
            fma2(a0, wr[c].x, hv.x);
            fma2(a1, wr[c].y, hv.y);
            ulonglong2 hw = hb[c + 1];
            fma2(a2, wr[c + 1].x, hw.x);
            fma2(a3, wr[c + 1].y, hw.y);
        }
        u64 s01 = add2(add2(a0, a1), add2(a2, a3));
        float2 f = unpk(s01);
        float dot = f.x + f.y;

        if (kq) part[((kq - 1) << 8) + j] = dot;
        __syncthreads();                      // B1: partials visible

        if (kq == 0) {
            float hn = fast_tanh(p + dot + part[j] + part[256 + j] + part[512 + j]);
            hbuf[((step + 1) & 1) * 256 + j] = hn;
            if (WRITE_H)
                hout[((size_t)b * Tlen + step) * Hd + j] = hn;
        }
        __syncthreads();                      // B2: new h visible
        p = pn;
    }

    if (FINAL) {
        // final h in parity (Tlen & 1) == 0
        if (t < 64) {
            int o = t >> 5, lane = t & 31;
            float s = 0.f;
            #pragma unroll
            for (int q = 0; q < 8; ++q) {
                int jj = lane + (q << 5);
                s += hbuf[jj] * fcw[o * Hd + jj];
            }
            #pragma unroll
            for (int off = 16; off; off >>= 1)
                s += __shfl_down_sync(0xffffffffu, s, off);
            if (lane == 0) out[b * NOUT + o] = s + fcb[o];
        }
    }
}

extern "C" void kernel_launch(void* const* d_in, const int* in_sizes, int n_in,
                              void* d_out, int out_size) {
    const float* x    = (const float*)d_in[0];
    const float* Wxh0 = (const float*)d_in[1];
    const float* Whh0 = (const float*)d_in[2];
    const float* b0   = (const float*)d_in[3];
    const float* Wxh1 = (const float*)d_in[4];
    const float* Whh1 = (const float*)d_in[5];
    const float* b1   = (const float*)d_in[6];
    const float* fcw  = (const float*)d_in[7];
    const float* fcb  = (const float*)d_in[8];
    float* out = (float*)d_out;

    float *bufA = nullptr, *bufB = nullptr;
    cudaGetSymbolAddress((void**)&bufA, g_bufA);
    cudaGetSymbolAddress((void**)&bufB, g_bufB);

    cudaFuncSetAttribute(gemm_kernel,
        cudaFuncAttributeMaxDynamicSharedMemorySize, GEMM_SMEM);

    // Layer 1
    gemm_kernel<<<2048, 256, GEMM_SMEM>>>(x, Wxh0, b0, bufA);
    recur_kernel<true, false><<<Bsz, 1024>>>(
        bufA, Whh0, bufB, nullptr, nullptr, nullptr);

    // Layer 2 + head
    gemm_kernel<<<2048, 256, GEMM_SMEM>>>(bufB, Wxh1, b1, bufA);
    recur_kernel<false, true><<<Bsz, 1024>>>(
        bufA, Whh1, nullptr, fcw, fcb, out);
}

// round 8
// speedup vs baseline: 1.5705x; 1.5705x over previous
#include <cuda_runtime.h>
#include <math.h>

#define Bsz  128
#define Tlen 1024
#define Hd   256
#define NOUT 2

typedef unsigned long long u64;

// Scratch buffers (device globals — allocation is forbidden)
__device__ float g_bufA[Bsz * Tlen * Hd];  // pre-activations
__device__ float g_bufB[Bsz * Tlen * Hd];  // layer-1 hidden states

// ---------- packed fp32x2 helpers (full-rate fp32 path on sm_103a) ----------
__device__ __forceinline__ void fma2(u64& acc, u64 a, u64 b) {
    asm("fma.rn.f32x2 %0, %1, %2, %0;" : "+l"(acc) : "l"(a), "l"(b));
}
__device__ __forceinline__ u64 add2(u64 a, u64 b) {
    u64 r; asm("add.rn.f32x2 %0, %1, %2;" : "=l"(r) : "l"(a), "l"(b)); return r;
}
__device__ __forceinline__ float2 unpk(u64 v) {
    float2 r; asm("mov.b64 {%0, %1}, %2;" : "=f"(r.x), "=f"(r.y) : "l"(v)); return r;
}

// =============================================================================
// GEMM (R6 version — known good, ~449us): out = A @ W^T + bias
// M=131072, N=K=256. Tile 128x128, 256 threads, K staged in 4 chunks of 64.
// A staged DUPLICATED so the m-operand loads as one LDS.64.
// =============================================================================
#define WS_STRIDE 130
#define AS_STRIDE 258
#define GEMM_SMEM ((Hd * WS_STRIDE + 64 * AS_STRIDE) * 4)

__global__ void __launch_bounds__(256, 1) gemm_kernel(
    const float* __restrict__ A, const float* __restrict__ W,
    const float* __restrict__ bias, float* __restrict__ out)
{
    extern __shared__ float sm[];
    float* Ws = sm;                    // [K=256][130]
    float* As = sm + Hd * WS_STRIDE;   // [64][258]

    const int t   = threadIdx.x;
    const int nt  = blockIdx.x & 1;
    const int mt  = blockIdx.x >> 1;
    const int m0  = mt * 128, n0 = nt * 128;
    const int kq  = t & 15;
    const int rn  = t >> 4;
    const int ml  = t & 15;
    const int tn2 = (t >> 4) << 1;

    const float4* W4 = (const float4*)(W + (size_t)n0 * Hd);
    #pragma unroll
    for (int p = 0; p < 8; ++p) {
        int row = rn + (p << 4);
        #pragma unroll
        for (int q = 0; q < 4; ++q) {
            float4 v = W4[row * 64 + (q << 4) + kq];
            int k = (((q << 4) + kq) << 2);
            Ws[(k + 0) * WS_STRIDE + row] = v.x;
            Ws[(k + 1) * WS_STRIDE + row] = v.y;
            Ws[(k + 2) * WS_STRIDE + row] = v.z;
            Ws[(k + 3) * WS_STRIDE + row] = v.w;
        }
    }

    u64 acc[8][4];
    #pragma unroll
    for (int i = 0; i < 8; ++i)
        #pragma unroll
        for (int j = 0; j < 4; ++j) acc[i][j] = 0ull;

    const float4* A4 = (const float4*)(A + (size_t)m0 * Hd);

    float4 v[8];
    #pragma unroll
    for (int p = 0; p < 8; ++p)
        v[p] = A4[(rn + (p << 4)) * 64 + kq];

    for (int s = 0; s < 4; ++s) {
        __syncthreads();
        #pragma unroll
        for (int p = 0; p < 8; ++p) {
            int row2 = (rn + (p << 4)) << 1;
            int k0 = kq << 2;
            *(float2*)&As[(k0 + 0) * AS_STRIDE + row2] = make_float2(v[p].x, v[p].x);
            *(float2*)&As[(k0 + 1) * AS_STRIDE + row2] = make_float2(v[p].y, v[p].y);
            *(float2*)&As[(k0 + 2) * AS_STRIDE + row2] = make_float2(v[p].z, v[p].z);
            *(float2*)&As[(k0 + 3) * AS_STRIDE + row2] = make_float2(v[p].w, v[p].w);
        }
        if (s < 3) {
            #pragma unroll
            for (int p = 0; p < 8; ++p)
                v[p] = A4[(rn + (p << 4)) * 64 + ((s + 1) << 4) + kq];
        }
        __syncthreads();

        const int kbase = s << 6;
        #pragma unroll 4
        for (int kk = 0; kk < 64; ++kk) {
            u64 ad[8];
            #pragma unroll
            for (int i = 0; i < 8; ++i)
                ad[i] = *(const u64*)&As[kk * AS_STRIDE + ((ml + (i << 4)) << 1)];
            u64 bp[4];
            #pragma unroll
            for (int j = 0; j < 4; ++j)
                bp[j] = *(const u64*)&Ws[(kbase + kk) * WS_STRIDE + tn2 + (j << 5)];
            #pragma unroll
            for (int i = 0; i < 8; ++i)
                #pragma unroll
                for (int j = 0; j < 4; ++j)
                    fma2(acc[i][j], ad[i], bp[j]);
        }
    }

    #pragma unroll
    for (int j = 0; j < 4; ++j) {
        int n = n0 + tn2 + (j << 5);
        float bv0 = bias[n], bv1 = bias[n + 1];
        #pragma unroll
        for (int i = 0; i < 8; ++i) {
            int m = m0 + ml + (i << 4);
            float2 vv = unpk(acc[i][j]);
            float2 r; r.x = vv.x + bv0; r.y = vv.y + bv1;
            *(float2*)&out[(size_t)m * Hd + n] = r;
        }
    }
}

// =============================================================================
// Recurrence v6: 1 CTA = 1 batch row, 512 threads (16 warps).
// Thread t -> output j = t & 255, K-half kh = t >> 8 (WARP-UNIFORM).
// -> every h LDS.128 is a single-address warp broadcast (1 wavefront).
// Weights/thread = 128 floats: 80 in registers + 48 in smem (no-spill split).
// 2-way cross-warp reduce via part[] with 2 barriers/step.
// =============================================================================
#define RREG 20   // float4 in registers (80 floats)
#define RSM  12   // float4 in smem (48 floats)
#define REC_SMEM ((2 * 256 + 256) * 4 + RSM * 512 * 16)

__device__ __forceinline__ float fast_tanh(float x) {
    float e = __expf(2.0f * x);
    return 1.0f - 2.0f * __fdividef(1.0f, e + 1.0f);
}

template<bool WRITE_H, bool FINAL>
__global__ void __launch_bounds__(512, 1) recur_kernel(
    const float* __restrict__ pre, const float* __restrict__ Whh,
    float* __restrict__ hout,
    const float* __restrict__ fcw, const float* __restrict__ fcb,
    float* __restrict__ out)
{
    extern __shared__ float smf[];
    float* hbuf = smf;                 // [2][256] ping-pong h
    float* part = smf + 512;           // [256] partial dots from kh=1
    ulonglong2* Wsm = (ulonglong2*)(smf + 768);   // [RSM][512]

    const int t  = threadIdx.x;
    const int b  = blockIdx.x;
    const int j  = t & 255;
    const int kh = t >> 8;             // 0 or 1, uniform within each warp

    // This thread's 128 weights: 20 f4 -> regs, 12 f4 -> smem
    const ulonglong2* wg =
        (const ulonglong2*)(Whh + (size_t)j * Hd + (kh << 7));
    ulonglong2 wr[RREG];
    #pragma unroll
    for (int c = 0; c < RREG; ++c) wr[c] = wg[c];
    #pragma unroll
    for (int c = 0; c < RSM; ++c) Wsm[c * 512 + t] = wg[RREG + c];

    if (t < 512) hbuf[t] = 0.f;        // h0 = 0 in both parities

    const float* preb = pre + (size_t)b * Tlen * Hd;
    float p = (kh == 0) ? preb[j] : 0.f;
    __syncthreads();

    for (int step = 0; step < Tlen; ++step) {
        float pn = 0.f;
        if (kh == 0) {
            int sn = (step + 1 < Tlen) ? step + 1 : step;
            pn = preb[sn * Hd + j];    // prefetch next pre
        }

        // h chunk base for this K-half: broadcast addresses (warp-uniform)
        const ulonglong2* hb =
            (const ulonglong2*)(hbuf + (step & 1) * 256 + (kh << 7));

        u64 a0 = 0ull, a1 = 0ull, a2 = 0ull, a3 = 0ull, a4 = 0ull, a5 = 0ull;

        // smem-resident weights first: fills the LSU pipe early
        #pragma unroll
        for (int c = 0; c < RSM; ++c) {
            ulonglong2 hv = hb[RREG + c];
            ulonglong2 wv = Wsm[c * 512 + t];
            fma2(a4, wv.x, hv.x);
            fma2(a5, wv.y, hv.y);
        }
        #pragma unroll
        for (int c = 0; c < RREG; c += 2) {
            ulonglong2 hv = hb[c];
            fma2(a0, wr[c].x, hv.x);
            fma2(a1, wr[c].y, hv.y);
            ulonglong2 hw = hb[c + 1];
            fma2(a2, wr[c + 1].x, hw.x);
            fma2(a3, wr[c + 1].y, hw.y);
        }

        u64 s01 = add2(add2(add2(a0, a1), add2(a2, a3)), add2(a4, a5));
        float2 f = unpk(s01);
        float dot = f.x + f.y;

        if (kh) part[j] = dot;
        __syncthreads();               // B1: partials visible

        if (kh == 0) {
            float hn = fast_tanh(p + dot + part[j]);
            hbuf[((step + 1) & 1) * 256 + j] = hn;
            if (WRITE_H)
                hout[((size_t)b * Tlen + step) * Hd + j] = hn;
        }
        __syncthreads();               // B2: new h visible
        p = pn;
    }

    if (FINAL) {
        // final h in parity (Tlen & 1) == 0
        if (t < 64) {
            int o = t >> 5, lane = t & 31;
            float s = 0.f;
            #pragma unroll
            for (int q = 0; q < 8; ++q) {
                int jj = lane + (q << 5);
                s += hbuf[jj] * fcw[o * Hd + jj];
            }
            #pragma unroll
            for (int off = 16; off; off >>= 1)
                s += __shfl_down_sync(0xffffffffu, s, off);
            if (lane == 0) out[b * NOUT + o] = s + fcb[o];
        }
    }
}

extern "C" void kernel_launch(void* const* d_in, const int* in_sizes, int n_in,
                              void* d_out, int out_size) {
    const float* x    = (const float*)d_in[0];
    const float* Wxh0 = (const float*)d_in[1];
    const float* Whh0 = (const float*)d_in[2];
    const float* b0   = (const float*)d_in[3];
    const float* Wxh1 = (const float*)d_in[4];
    const float* Whh1 = (const float*)d_in[5];
    const float* b1   = (const float*)d_in[6];
    const float* fcw  = (const float*)d_in[7];
    const float* fcb  = (const float*)d_in[8];
    float* out = (float*)d_out;

    float *bufA = nullptr, *bufB = nullptr;
    cudaGetSymbolAddress((void**)&bufA, g_bufA);
    cudaGetSymbolAddress((void**)&bufB, g_bufB);

    cudaFuncSetAttribute(gemm_kernel,
        cudaFuncAttributeMaxDynamicSharedMemorySize, GEMM_SMEM);
    cudaFuncSetAttribute(recur_kernel<true, false>,
        cudaFuncAttributeMaxDynamicSharedMemorySize, REC_SMEM);
    cudaFuncSetAttribute(recur_kernel<false, true>,
        cudaFuncAttributeMaxDynamicSharedMemorySize, REC_SMEM);

    // Layer 1
    gemm_kernel<<<2048, 256, GEMM_SMEM>>>(x, Wxh0, b0, bufA);
    recur_kernel<true, false><<<Bsz, 512, REC_SMEM>>>(
        bufA, Whh0, bufB, nullptr, nullptr, nullptr);

    // Layer 2 + head
    gemm_kernel<<<2048, 256, GEMM_SMEM>>>(bufB, Wxh1, b1, bufA);
    recur_kernel<false, true><<<Bsz, 512, REC_SMEM>>>(
        bufA, Whh1, nullptr, fcw, fcb, out);
}